// round 11
// baseline (speedup 1.0000x reference)
#include <cuda_runtime.h>
#include <cuda_fp16.h>
#include <cuda_bf16.h>
#include <math.h>
#include <stdint.h>

// Problem constants
#define BT   4096      // B*S tokens
#define DD   1024
#define HH   2048
#define OO   1024
#define EE   8
#define TOPK 2
#define NPAIR (BT*TOPK)    // 8192
#define NPADMAX (NPAIR + EE*128)   // 9216 padded positions
#define MAXTILE 71
#define OUT_TENSOR (BT*OO) // 4194304

// ================= small helpers =================
__device__ __forceinline__ uint32_t smem_to_u32(const void* p) {
    uint32_t a;
    asm("{ .reg .u64 t; cvta.to.shared.u64 t, %1; cvt.u32.u64 %0, t; }" : "=r"(a) : "l"(p));
    return a;
}
#define CP_ASYNC16(dst, src) \
    asm volatile("cp.async.ca.shared.global [%0], [%1], 16;" :: "r"(dst), "l"(src))
#define CP_COMMIT() asm volatile("cp.async.commit_group;" ::: "memory")
#define CP_WAIT1()  asm volatile("cp.async.wait_group 1;" ::: "memory")
#define CP_WAIT0()  asm volatile("cp.async.wait_group 0;" ::: "memory")

__device__ __forceinline__ void ldsm_x4(uint32_t& r0, uint32_t& r1, uint32_t& r2, uint32_t& r3,
                                        uint32_t addr) {
    asm volatile("ldmatrix.sync.aligned.m8n8.x4.shared.b16 {%0,%1,%2,%3}, [%4];"
                 : "=r"(r0), "=r"(r1), "=r"(r2), "=r"(r3) : "r"(addr));
}
__device__ __forceinline__ void ldsm_x4_t(uint32_t& r0, uint32_t& r1, uint32_t& r2, uint32_t& r3,
                                          uint32_t addr) {
    asm volatile("ldmatrix.sync.aligned.m8n8.x4.trans.shared.b16 {%0,%1,%2,%3}, [%4];"
                 : "=r"(r0), "=r"(r1), "=r"(r2), "=r"(r3) : "r"(addr));
}
__device__ __forceinline__ void mma_f16(float& c0, float& c1, float& c2, float& c3,
                                        uint32_t a0, uint32_t a1, uint32_t a2, uint32_t a3,
                                        uint32_t b0, uint32_t b1) {
    asm volatile(
        "mma.sync.aligned.m16n8k16.row.col.f32.f16.f16.f32 "
        "{%0,%1,%2,%3}, {%4,%5,%6,%7}, {%8,%9}, {%0,%1,%2,%3};"
        : "+f"(c0), "+f"(c1), "+f"(c2), "+f"(c3)
        : "r"(a0), "r"(a1), "r"(a2), "r"(a3), "r"(b0), "r"(b1));
}

// ================= scratch =================
__device__ __half d_h1[(size_t)NPADMAX * HH];        // 37.8 MB
__device__ __half d_h2[(size_t)NPADMAX * HH];        // 37.8 MB
__device__ __half d_xh[(size_t)BT * DD];             // 8 MB (fp16 x)
__device__ __half d_w1h[(size_t)EE * DD * HH];       // 32 MB  [E][D][H] (K x N row-major)
__device__ __half d_w2h[(size_t)EE * HH * HH];       // 64 MB
__device__ __half d_w3h[(size_t)EE * HH * OO];       // 32 MB
__device__ float  d_y[(size_t)NPADMAX * OO];         // 37.8 MB gated partials by position
__device__ float d_probs[(size_t)BT * EE];           // full softmax probs per token
__device__ int   d_pair_token[NPADMAX];
__device__ float d_pair_gate[NPADMAX];
__device__ int   d_pair_pos[NPAIR];                  // pair j -> padded position
__device__ int   d_counts[EE];
__device__ int   d_offsets[EE];                      // padded (128-aligned) offsets
__device__ int   d_cursor[EE];
__device__ int   d_top_idx[NPAIR];
__device__ float d_top_g[NPAIR];
__device__ int   d_tile_e[MAXTILE];
__device__ int   d_tile_row0[MAXTILE];
__device__ int   d_ntiles;

// ================= fused pre: weight fp32->fp16 convert + gating ==============
#define N1 ((size_t)EE * DD * HH)   // 16,777,216
#define N2 ((size_t)EE * HH * HH)   // 33,554,432
#define N3 ((size_t)EE * HH * OO)   // 16,777,216
#define NCONVB 32768u               // (N1+N2+N3)/8/256

__global__ __launch_bounds__(256)
void fused_pre_kernel(const float* __restrict__ W1,
                      const float* __restrict__ W2,
                      const float* __restrict__ W3,
                      const float* __restrict__ x,
                      const float* __restrict__ Wg,
                      const float* __restrict__ bg) {
    if (blockIdx.x < NCONVB) {
        size_t i8 = ((size_t)blockIdx.x * 256 + threadIdx.x) * 8;
        const float* src;
        __half* dst;
        size_t off;
        if (i8 < N1)            { src = W1; dst = d_w1h; off = i8; }
        else if (i8 < N1 + N2)  { src = W2; dst = d_w2h; off = i8 - N1; }
        else                    { src = W3; dst = d_w3h; off = i8 - N1 - N2; }
        float4 f0 = *(const float4*)(src + off);
        float4 f1 = *(const float4*)(src + off + 4);
        __half2 h[4];
        h[0] = __floats2half2_rn(f0.x, f0.y);
        h[1] = __floats2half2_rn(f0.z, f0.w);
        h[2] = __floats2half2_rn(f1.x, f1.y);
        h[3] = __floats2half2_rn(f1.z, f1.w);
        *(uint4*)(dst + off) = *(uint4*)h;
        return;
    }
    // -------- gating: one token per block (atomic-free) --------
    int t = blockIdx.x - NCONVB;
    int tid = threadIdx.x;        // 256 threads
    float acc[EE];
#pragma unroll
    for (int e = 0; e < EE; e++) acc[e] = 0.0f;
    const float* xr = x + (size_t)t * DD;
    __half* xh = d_xh + (size_t)t * DD;
    for (int d = tid; d < DD; d += 256) {
        float xv = xr[d];
        xh[d] = __float2half(xv);
        const float* w = Wg + (size_t)d * EE;
#pragma unroll
        for (int e = 0; e < EE; e++) acc[e] += xv * w[e];
    }
#pragma unroll
    for (int e = 0; e < EE; e++) {
#pragma unroll
        for (int off = 16; off > 0; off >>= 1)
            acc[e] += __shfl_down_sync(0xffffffffu, acc[e], off);
    }
    __shared__ float sred[8][EE];
    int warp = tid >> 5, lane = tid & 31;
    if (lane == 0) {
#pragma unroll
        for (int e = 0; e < EE; e++) sred[warp][e] = acc[e];
    }
    __syncthreads();
    if (tid == 0) {
        float logit[EE];
#pragma unroll
        for (int e = 0; e < EE; e++) {
            float s = sred[0][e];
#pragma unroll
            for (int w = 1; w < 8; w++) s += sred[w][e];
            logit[e] = s + bg[e];
        }
        float m = logit[0];
#pragma unroll
        for (int e = 1; e < EE; e++) m = fmaxf(m, logit[e]);
        float p[EE], se = 0.0f;
#pragma unroll
        for (int e = 0; e < EE; e++) { p[e] = __expf(logit[e] - m); se += p[e]; }
        float inv = 1.0f / se;
#pragma unroll
        for (int e = 0; e < EE; e++) p[e] *= inv;
        *(float4*)(d_probs + (size_t)t * EE)     = make_float4(p[0], p[1], p[2], p[3]);
        *(float4*)(d_probs + (size_t)t * EE + 4) = make_float4(p[4], p[5], p[6], p[7]);
        int i0 = 0;
#pragma unroll
        for (int e = 1; e < EE; e++) if (logit[e] > logit[i0]) i0 = e;
        int i1 = (i0 == 0) ? 1 : 0;
#pragma unroll
        for (int e = 0; e < EE; e++)
            if (e != i0 && logit[e] > logit[i1]) i1 = e;
        float l0 = logit[i0], l1 = logit[i1];
        float mm = fmaxf(l0, l1);
        float e0 = __expf(l0 - mm), e1 = __expf(l1 - mm);
        float s2 = e0 + e1;
        d_top_idx[t * 2 + 0] = i0;  d_top_g[t * 2 + 0] = e0 / s2;
        d_top_idx[t * 2 + 1] = i1;  d_top_g[t * 2 + 1] = e1 / s2;
    }
}

// ================= stats: counts, padded offsets, tile map, aux outputs ========
__global__ __launch_bounds__(512)
void stats_kernel(float* __restrict__ out, int out_size) {
    __shared__ float sprob[EE];
    __shared__ float sgate[EE];
    __shared__ int   scnt[EE];
    int tid = threadIdx.x;
    if (tid < EE) { sprob[tid] = 0.0f; sgate[tid] = 0.0f; scnt[tid] = 0; }
    __syncthreads();
    float lp[EE];
    float lg[EE];
    int   lc[EE];
#pragma unroll
    for (int e = 0; e < EE; e++) { lp[e] = 0.0f; lg[e] = 0.0f; lc[e] = 0; }
    for (int t = tid; t < BT; t += 512) {
        const float* p = d_probs + (size_t)t * EE;
#pragma unroll
        for (int e = 0; e < EE; e++) lp[e] += p[e];
    }
    for (int j = tid; j < NPAIR; j += 512) {
        int e = d_top_idx[j];
        lg[e] += d_top_g[j];
        lc[e]++;
    }
#pragma unroll
    for (int e = 0; e < EE; e++) {
        atomicAdd(&sprob[e], lp[e]);
        atomicAdd(&sgate[e], lg[e]);
        atomicAdd(&scnt[e], lc[e]);
    }
    __syncthreads();
    if (tid == 0) {
        int off = 0, nt = 0;
        for (int e = 0; e < EE; e++) {
            d_counts[e] = scnt[e];
            d_offsets[e] = off;
            d_cursor[e] = 0;
            int nti = (scnt[e] + 127) >> 7;
            for (int k = 0; k < nti; k++) {
                d_tile_e[nt] = e;
                d_tile_row0[nt] = off + k * 128;
                nt++;
            }
            off += nti * 128;
        }
        d_ntiles = nt;
        for (int i = OUT_TENSOR; i < out_size; i++) out[i] = 0.0f;
        float lb = 0.0f, ent = 0.0f;
        const float invT = 1.0f / (float)BT;
        for (int e = 0; e < EE; e++) {
            float ap = sprob[e] * invT;
            float ac = sgate[e] * invT;
            lb += ap * ac;
            ent -= ap * logf(ap + 1e-8f);
            out[OUT_TENSOR + 1 + e] = ac;
        }
        out[OUT_TENSOR] = 0.01f * (float)EE * lb;
        out[OUT_TENSOR + 1 + EE] = ent;
    }
}

// ================= scatter =================
__global__ void scatter_kernel() {
    int j = blockIdx.x * blockDim.x + threadIdx.x;
    if (j >= NPAIR) return;
    int t = j >> 1;
    int e = d_top_idx[j];
    int pos = d_offsets[e] + atomicAdd(&d_cursor[e], 1);
    d_pair_token[pos] = t;
    d_pair_gate[pos]  = d_top_g[j];
    d_pair_pos[j] = pos;
}

// ================= fp16 mma.sync expert GEMM =================
// CTA 128x128, 128 threads (4 warps, 2m x 2n), warp tile 64x64.
// Per k16-step per warp: 8 ldmatrix -> 32 MMA (4 MMA/LDSM).
// KC=64, 3-stage cp.async, XOR-swizzled smem.
#define KC 64
#define STAGE_BYTES 32768            // A 16KB + B 16KB
#define HDR_BYTES 2048               // [0:1024) A row ptrs, [1024:1536) gates
#define NSTAGE 3
#define SMEM_DYN (HDR_BYTES + NSTAGE*STAGE_BYTES)

template<int LAYER>
__global__ __launch_bounds__(128, 2)
void expert_gemm_mma(const __half* __restrict__ Wh,
                     const float* __restrict__ bias) {
    constexpr int Kd = (LAYER == 1) ? DD : HH;
    constexpr int Nd = (LAYER == 3) ? OO : HH;
    constexpr int NCH = Kd / KC;   // 16 or 32

    const int ti = blockIdx.y;
    if (ti >= d_ntiles) return;
    const int e    = d_tile_e[ti];
    const int row0 = d_tile_row0[ti];
    const int lim  = d_offsets[e] + d_counts[e];
    const int nblk = blockIdx.x;

    extern __shared__ char smem_raw[];
    const uint32_t sb = smem_to_u32(smem_raw);
    const char** sAptr = (const char**)smem_raw;        // [128] A row base pointers
    float* sgate = (float*)(smem_raw + 1024);           // [128]

    const int tid = threadIdx.x;      // 128
    const int wid = tid >> 5;         // 0..3
    const int lid = tid & 31;
    const int g   = lid >> 2;
    const int tg  = lid & 3;
    const int m0  = (wid & 1) * 64;
    const int n0  = (wid >> 1) * 64;

    const __half* hsrc = (LAYER == 2) ? d_h1 : d_h2;
    {
        int idx = min(row0 + tid, lim - 1);
        if (LAYER == 1) {
            int tok = d_pair_token[idx];
            sAptr[tid] = (const char*)(d_xh + (size_t)tok * DD);
        } else {
            sAptr[tid] = (const char*)(hsrc + (size_t)idx * Kd);
        }
        sgate[tid] = d_pair_gate[idx];
    }
    __syncthreads();

    // ---- cp.async mappings (128 threads) ----
    // A tile: 128 rows x 128B (8 chunks); thread: chunk lsubA, rows lrowA+16i
    const int lsubA = tid & 7, lrowA = tid >> 3;   // lrowA 0..15
    // B tile: 64 rows x 256B (16 chunks); thread: chunk lsubB, rows lrowB+8i
    const int lsubB = tid & 15, lrowB = tid >> 4;  // lrowB 0..7

    const uint32_t swA = (uint32_t)(lrowA * 128 + ((lsubA ^ (lrowA & 7)) << 4));
    const uint32_t swB = (uint32_t)(lrowB * 256 + ((lsubB ^ (lrowB & 7)) << 4));
    const __half* WhE = Wh + (size_t)e * Kd * Nd + (size_t)(nblk * 128);
    const char* bbase = (const char*)(WhE + (size_t)lrowB * Nd) + lsubB * 16;
    const size_t brstride = (size_t)8 * Nd * sizeof(__half);   // 8 k-rows
    const size_t bstep = (size_t)KC * Nd * sizeof(__half);     // per-stage

    // ---- ldmatrix lane constants ----
    const int til = lid >> 3, rin = lid & 7;
    const int thi = til >> 1, tlo = til & 1;
    uint32_t rowbaseA[4];
#pragma unroll
    for (int mt = 0; mt < 4; mt++)
        rowbaseA[mt] = (uint32_t)((m0 + mt * 16 + rin + tlo * 8) * 128);
    uint32_t koffA[4];
#pragma unroll
    for (int ks = 0; ks < 4; ks++)
        koffA[ks] = (uint32_t)((((ks * 2) + thi) ^ rin) << 4);
    const int klane = rin + tlo * 8;   // 0..15
    uint32_t lbB[4];
#pragma unroll
    for (int pr = 0; pr < 4; pr++) {
        int nc = (n0 >> 3) + pr * 2 + thi;
        lbB[pr] = (uint32_t)(klane * 256 + ((nc ^ rin) << 4));
    }

    float acc[4][8][4];
#pragma unroll
    for (int mt = 0; mt < 4; mt++)
#pragma unroll
        for (int nt = 0; nt < 8; nt++)
#pragma unroll
            for (int c = 0; c < 4; c++) acc[mt][nt][c] = 0.0f;

    auto issue = [&](int s) {
        uint32_t sa = sb + HDR_BYTES + (s % NSTAGE) * STAGE_BYTES;
        uint32_t sB = sa + 16384;
        size_t aoff = (size_t)s * 128;          // 64 halves along K
        size_t boff = (size_t)s * bstep;
#pragma unroll
        for (int i = 0; i < 8; i++)
            CP_ASYNC16(sa + swA + i * 2048, sAptr[lrowA + 16 * i] + lsubA * 16 + aoff);
#pragma unroll
        for (int i = 0; i < 8; i++)
            CP_ASYNC16(sB + swB + i * 2048, bbase + i * brstride + boff);
    };

    issue(0); CP_COMMIT();
    issue(1); CP_COMMIT();

    for (int c = 0; c < NCH; c++) {
        if (c + 1 < NCH) { CP_WAIT1(); } else { CP_WAIT0(); }
        __syncthreads();
        if (c + 2 < NCH) { issue(c + 2); CP_COMMIT(); }

        uint32_t sa = sb + HDR_BYTES + (c % NSTAGE) * STAGE_BYTES;
        uint32_t sB = sa + 16384;
#pragma unroll
        for (int ks = 0; ks < 4; ks++) {
            uint32_t b[16];
#pragma unroll
            for (int pr = 0; pr < 4; pr++)
                ldsm_x4_t(b[4*pr], b[4*pr+1], b[4*pr+2], b[4*pr+3],
                          sB + lbB[pr] + ks * 4096);
#pragma unroll
            for (int mt = 0; mt < 4; mt++) {
                uint32_t a0, a1, a2, a3;
                ldsm_x4(a0, a1, a2, a3, sa + rowbaseA[mt] + koffA[ks]);
#pragma unroll
                for (int nt = 0; nt < 8; nt++) {
                    int bi = (nt >> 1) * 4 + (nt & 1) * 2;
                    mma_f16(acc[mt][nt][0], acc[mt][nt][1], acc[mt][nt][2], acc[mt][nt][3],
                            a0, a1, a2, a3, b[bi], b[bi + 1]);
                }
            }
        }
    }

    // ---- epilogue ----
    const float* biasE = bias + (size_t)e * Nd + nblk * 128;
    __half* hdst = (LAYER == 1) ? d_h1 : d_h2;

#pragma unroll
    for (int mt = 0; mt < 4; mt++) {
#pragma unroll
        for (int nt = 0; nt < 8; nt++) {
            int col = n0 + nt * 8 + tg * 2;
            float bv0 = biasE[col], bv1 = biasE[col + 1];
#pragma unroll
            for (int half = 0; half < 2; half++) {
                int lr = m0 + mt * 16 + g + half * 8;
                int grow = row0 + lr;
                if (grow >= lim) continue;
                float v0 = acc[mt][nt][half * 2 + 0] + bv0;
                float v1 = acc[mt][nt][half * 2 + 1] + bv1;
                if (LAYER != 3) {
                    __half2 v = __floats2half2_rn(fmaxf(v0, 0.0f), fmaxf(v1, 0.0f));
                    *(__half2*)(hdst + (size_t)grow * HH + nblk * 128 + col) = v;
                } else {
                    float gt = sgate[lr];
                    float2 v = make_float2(gt * v0, gt * v1);
                    *(float2*)(d_y + (size_t)grow * OO + nblk * 128 + col) = v;
                }
            }
        }
    }
}

// ================= combine: out[t] = y[pos(2t)] + y[pos(2t+1)] =================
__global__ void combine_kernel(float* __restrict__ out) {
    int t = blockIdx.x;
    int p0 = d_pair_pos[2 * t];
    int p1 = d_pair_pos[2 * t + 1];
    const float4* y0 = (const float4*)(d_y + (size_t)p0 * OO);
    const float4* y1 = (const float4*)(d_y + (size_t)p1 * OO);
    float4* dst = (float4*)(out + (size_t)t * OO);
    int i = threadIdx.x;             // 256 threads, 256 float4 per row
    float4 a = y0[i], b = y1[i];
    dst[i] = make_float4(a.x + b.x, a.y + b.y, a.z + b.z, a.w + b.w);
}

// ================= launch =================
extern "C" void kernel_launch(void* const* d_in, const int* in_sizes, int n_in,
                              void* d_out, int out_size) {
    const float* x  = (const float*)d_in[0];
    const float* Wg = (const float*)d_in[1];
    const float* bg = (const float*)d_in[2];
    const float* W1 = (const float*)d_in[3];
    const float* b1 = (const float*)d_in[4];
    const float* W2 = (const float*)d_in[5];
    const float* b2 = (const float*)d_in[6];
    const float* W3 = (const float*)d_in[7];
    const float* b3 = (const float*)d_in[8];
    float* out = (float*)d_out;

    cudaFuncSetAttribute(expert_gemm_mma<1>, cudaFuncAttributeMaxDynamicSharedMemorySize, SMEM_DYN);
    cudaFuncSetAttribute(expert_gemm_mma<2>, cudaFuncAttributeMaxDynamicSharedMemorySize, SMEM_DYN);
    cudaFuncSetAttribute(expert_gemm_mma<3>, cudaFuncAttributeMaxDynamicSharedMemorySize, SMEM_DYN);

    __half* w1h = nullptr; cudaGetSymbolAddress((void**)&w1h, d_w1h);
    __half* w2h = nullptr; cudaGetSymbolAddress((void**)&w2h, d_w2h);
    __half* w3h = nullptr; cudaGetSymbolAddress((void**)&w3h, d_w3h);

    fused_pre_kernel<<<NCONVB + BT, 256>>>(W1, W2, W3, x, Wg, bg);           // 1
    stats_kernel<<<1, 512>>>(out, out_size);                                 // 2
    scatter_kernel<<<NPAIR / 256, 256>>>();                                  // 3
    expert_gemm_mma<1><<<dim3(HH/128, MAXTILE), 128, SMEM_DYN>>>(w1h, b1);   // 4
    expert_gemm_mma<2><<<dim3(HH/128, MAXTILE), 128, SMEM_DYN>>>(w2h, b2);   // 5
    expert_gemm_mma<3><<<dim3(OO/128, MAXTILE), 128, SMEM_DYN>>>(w3h, b3);   // 6
    combine_kernel<<<BT, 256>>>(out);                                        // 7
}

// round 12
// speedup vs baseline: 1.0993x; 1.0993x over previous
#include <cuda_runtime.h>
#include <cuda_fp16.h>
#include <cuda_bf16.h>
#include <math.h>
#include <stdint.h>

// Problem constants
#define BT   4096      // B*S tokens
#define DD   1024
#define HH   2048
#define OO   1024
#define EE   8
#define TOPK 2
#define NPAIR (BT*TOPK)    // 8192
#define OUT_TENSOR (BT*OO) // 4194304

// ================= small helpers =================
__device__ __forceinline__ uint32_t smem_to_u32(const void* p) {
    uint32_t a;
    asm("{ .reg .u64 t; cvta.to.shared.u64 t, %1; cvt.u32.u64 %0, t; }" : "=r"(a) : "l"(p));
    return a;
}
#define CP_ASYNC16(dst, src) \
    asm volatile("cp.async.ca.shared.global [%0], [%1], 16;" :: "r"(dst), "l"(src))
#define CP_ASYNC16_CG(dst, src) \
    asm volatile("cp.async.cg.shared.global [%0], [%1], 16;" :: "r"(dst), "l"(src))
#define CP_COMMIT() asm volatile("cp.async.commit_group;" ::: "memory")
#define CP_WAIT1()  asm volatile("cp.async.wait_group 1;" ::: "memory")
#define CP_WAIT0()  asm volatile("cp.async.wait_group 0;" ::: "memory")

__device__ __forceinline__ void ldsm_x4(uint32_t& r0, uint32_t& r1, uint32_t& r2, uint32_t& r3,
                                        uint32_t addr) {
    asm volatile("ldmatrix.sync.aligned.m8n8.x4.shared.b16 {%0,%1,%2,%3}, [%4];"
                 : "=r"(r0), "=r"(r1), "=r"(r2), "=r"(r3) : "r"(addr));
}
__device__ __forceinline__ void ldsm_x4_t(uint32_t& r0, uint32_t& r1, uint32_t& r2, uint32_t& r3,
                                          uint32_t addr) {
    asm volatile("ldmatrix.sync.aligned.m8n8.x4.trans.shared.b16 {%0,%1,%2,%3}, [%4];"
                 : "=r"(r0), "=r"(r1), "=r"(r2), "=r"(r3) : "r"(addr));
}
__device__ __forceinline__ void mma_f16(float& c0, float& c1, float& c2, float& c3,
                                        uint32_t a0, uint32_t a1, uint32_t a2, uint32_t a3,
                                        uint32_t b0, uint32_t b1) {
    asm volatile(
        "mma.sync.aligned.m16n8k16.row.col.f32.f16.f16.f32 "
        "{%0,%1,%2,%3}, {%4,%5,%6,%7}, {%8,%9}, {%0,%1,%2,%3};"
        : "+f"(c0), "+f"(c1), "+f"(c2), "+f"(c3)
        : "r"(a0), "r"(a1), "r"(a2), "r"(a3), "r"(b0), "r"(b1));
}

// ================= scratch =================
__device__ __half d_h1[(size_t)NPAIR * HH];          // 32 MB
__device__ __half d_h2[(size_t)NPAIR * HH];          // 32 MB
__device__ __half d_xh[(size_t)BT * DD];             // 8 MB (fp16 x)
__device__ __half d_w1h[(size_t)EE * DD * HH];       // 32 MB  [E][D][H] (K x N row-major)
__device__ __half d_w2h[(size_t)EE * HH * HH];       // 64 MB
__device__ __half d_w3h[(size_t)EE * HH * OO];       // 32 MB
__device__ float  d_y[(size_t)NPAIR * OO];           // 32 MB gated partial outputs by position
__device__ int   d_pair_token[NPAIR];
__device__ float d_pair_gate[NPAIR];
__device__ int   d_pair_pos[NPAIR];                  // pair j -> position
__device__ int   d_counts[EE];
__device__ int   d_offsets[EE];
__device__ int   d_cursor[EE];
__device__ float d_sum_probs[EE];
__device__ float d_sum_gates[EE];
__device__ int   d_top_idx[NPAIR];
__device__ float d_top_g[NPAIR];

// ================= fused weight convert fp32 -> fp16 =================
#define N1 ((size_t)EE * DD * HH)   // 16,777,216
#define N2 ((size_t)EE * HH * HH)   // 33,554,432
#define N3 ((size_t)EE * HH * OO)   // 16,777,216
__global__ void convert_w_kernel(const float* __restrict__ W1,
                                 const float* __restrict__ W2,
                                 const float* __restrict__ W3) {
    size_t gid = (size_t)blockIdx.x * blockDim.x + threadIdx.x;
    size_t i8 = gid * 8;
    const float* src;
    __half* dst;
    size_t off;
    if (i8 < N1)            { src = W1; dst = d_w1h; off = i8; }
    else if (i8 < N1 + N2)  { src = W2; dst = d_w2h; off = i8 - N1; }
    else                    { src = W3; dst = d_w3h; off = i8 - N1 - N2; }
    float4 f0 = *(const float4*)(src + off);
    float4 f1 = *(const float4*)(src + off + 4);
    __half2 h[4];
    h[0] = __floats2half2_rn(f0.x, f0.y);
    h[1] = __floats2half2_rn(f0.z, f0.w);
    h[2] = __floats2half2_rn(f1.x, f1.y);
    h[3] = __floats2half2_rn(f1.z, f1.w);
    *(uint4*)(dst + off) = *(uint4*)h;
}

// ================= gating (also emits fp16 x) =================
__global__ void gating_kernel(const float* __restrict__ x,
                              const float* __restrict__ Wg,
                              const float* __restrict__ bg) {
    int t = blockIdx.x;
    int tid = threadIdx.x;              // 128 threads
    float acc[EE];
#pragma unroll
    for (int e = 0; e < EE; e++) acc[e] = 0.0f;
    const float* xr = x + (size_t)t * DD;
    __half* xh = d_xh + (size_t)t * DD;
    for (int d = tid; d < DD; d += 128) {
        float xv = xr[d];
        xh[d] = __float2half(xv);
        const float* w = Wg + (size_t)d * EE;
#pragma unroll
        for (int e = 0; e < EE; e++) acc[e] += xv * w[e];
    }
#pragma unroll
    for (int e = 0; e < EE; e++) {
#pragma unroll
        for (int off = 16; off > 0; off >>= 1)
            acc[e] += __shfl_down_sync(0xffffffffu, acc[e], off);
    }
    __shared__ float sred[4][EE];
    int warp = tid >> 5, lane = tid & 31;
    if (lane == 0) {
#pragma unroll
        for (int e = 0; e < EE; e++) sred[warp][e] = acc[e];
    }
    __syncthreads();
    if (tid == 0) {
        float logit[EE];
#pragma unroll
        for (int e = 0; e < EE; e++)
            logit[e] = sred[0][e] + sred[1][e] + sred[2][e] + sred[3][e] + bg[e];
        float m = logit[0];
#pragma unroll
        for (int e = 1; e < EE; e++) m = fmaxf(m, logit[e]);
        float p[EE], se = 0.0f;
#pragma unroll
        for (int e = 0; e < EE; e++) { p[e] = __expf(logit[e] - m); se += p[e]; }
        float inv = 1.0f / se;
#pragma unroll
        for (int e = 0; e < EE; e++) atomicAdd(&d_sum_probs[e], p[e] * inv);
        int i0 = 0;
#pragma unroll
        for (int e = 1; e < EE; e++) if (logit[e] > logit[i0]) i0 = e;
        int i1 = (i0 == 0) ? 1 : 0;
#pragma unroll
        for (int e = 0; e < EE; e++)
            if (e != i0 && logit[e] > logit[i1]) i1 = e;
        float l0 = logit[i0], l1 = logit[i1];
        float mm = fmaxf(l0, l1);
        float e0 = __expf(l0 - mm), e1 = __expf(l1 - mm);
        float s2 = e0 + e1;
        float g0 = e0 / s2, g1 = e1 / s2;
        atomicAdd(&d_sum_gates[i0], g0);
        atomicAdd(&d_sum_gates[i1], g1);
        atomicAdd(&d_counts[i0], 1);
        atomicAdd(&d_counts[i1], 1);
        d_top_idx[t * 2 + 0] = i0;  d_top_g[t * 2 + 0] = g0;
        d_top_idx[t * 2 + 1] = i1;  d_top_g[t * 2 + 1] = g1;
    }
}

// tiny init for accumulators (before gating)
__global__ void init_acc_kernel() {
    if (threadIdx.x < EE) {
        d_counts[threadIdx.x] = 0;
        d_sum_probs[threadIdx.x] = 0.0f;
        d_sum_gates[threadIdx.x] = 0.0f;
    }
}

// ================= finalize: offsets + aux stats + tail-zero =================
__global__ void finalize_kernel(float* __restrict__ out, int out_size) {
    if (threadIdx.x == 0 && blockIdx.x == 0) {
        int off = 0;
        for (int e = 0; e < EE; e++) {
            d_offsets[e] = off;
            off += d_counts[e];
            d_cursor[e] = 0;
        }
        for (int i = OUT_TENSOR; i < out_size; i++) out[i] = 0.0f;  // tail is tiny
        float lb = 0.0f, ent = 0.0f;
        const float invT = 1.0f / (float)BT;
        for (int e = 0; e < EE; e++) {
            float ap = d_sum_probs[e] * invT;
            float ac = d_sum_gates[e] * invT;
            lb += ap * ac;
            ent -= ap * logf(ap + 1e-8f);
            out[OUT_TENSOR + 1 + e] = ac;
        }
        out[OUT_TENSOR] = 0.01f * (float)EE * lb;
        out[OUT_TENSOR + 1 + EE] = ent;
    }
}

// ================= scatter =================
__global__ void scatter_kernel() {
    int j = blockIdx.x * blockDim.x + threadIdx.x;
    if (j >= NPAIR) return;
    int t = j >> 1;
    int e = d_top_idx[j];
    int pos = d_offsets[e] + atomicAdd(&d_cursor[e], 1);
    d_pair_token[pos] = t;
    d_pair_gate[pos]  = d_top_g[j];
    d_pair_pos[j] = pos;
}

// ================= fp16 mma.sync expert GEMM (ldmatrix + 3-stage cp.async) ========
// CTA 128(M)x128(N), KC=64. A smem: [128][64h] m-major; B smem: [64][128h] k-major.
// warp grid 2(m) x 4(n); warp tile 64x32; mma m16n8k16 f32-accum.
// A loads .ca (shared across co-resident CTAs), B loads .cg (L1 bypass).
#define KC 64
#define STAGE_BYTES 32768            // A 16KB + B 16KB
#define HDR_BYTES 1024
#define NSTAGE 3
#define SMEM_DYN (HDR_BYTES + NSTAGE*STAGE_BYTES)

template<int LAYER>
__global__ __launch_bounds__(256, 2)
void expert_gemm_mma(const __half* __restrict__ Wh,
                     const float* __restrict__ bias) {
    constexpr int Kd = (LAYER == 1) ? DD : HH;
    constexpr int Nd = (LAYER == 3) ? OO : HH;
    constexpr int NCH = Kd / KC;   // 16 or 32

    const int e   = blockIdx.z;
    const int cnt = d_counts[e];
    const int mtile = blockIdx.y;
    if (mtile * 128 >= cnt) return;
    const int base = d_offsets[e];
    const int nblk = blockIdx.x;

    extern __shared__ char smem_raw[];
    const uint32_t sb = smem_to_u32(smem_raw);
    int* stok    = (int*)smem_raw;            // [128]
    float* sgate = (float*)(smem_raw + 512);  // [128]

    const int tid = threadIdx.x;
    const int wid = tid >> 5;
    const int lid = tid & 31;
    const int g   = lid >> 2;     // 0..7
    const int tg  = lid & 3;      // 0..3
    const int m0  = (wid & 1) * 64;
    const int n0  = (wid >> 1) * 32;

    if (tid < 128) {
        int gr = mtile * 128 + tid;
        int idx = base + min(gr, cnt - 1);
        stok[tid]  = d_pair_token[idx];
        sgate[tid] = d_pair_gate[idx];
    }
    __syncthreads();

    // ---- cp.async mappings ----
    const int lsubA = tid & 7, lrowA = tid >> 3;     // A: 128 rows x 128B
    const int lsubB = tid & 15, lrowB = tid >> 4;    // B: 64 rows x 256B

    const __half* WhE = Wh + (size_t)e * Kd * Nd + (size_t)(nblk * 128);
    const __half* hsrc = (LAYER == 2) ? d_h1 : d_h2;

    uint32_t dstoffA[4], dstoffB[4];
    const char* asrc[4];
    const char* bsrc[4];
#pragma unroll
    for (int i = 0; i < 4; i++) {
        int rA = lrowA + 32 * i;
        dstoffA[i] = (uint32_t)(rA * 128 + ((lsubA ^ (rA & 7)) << 4));
        if (LAYER == 1) {
            asrc[i] = (const char*)(d_xh + (size_t)stok[rA] * DD) + lsubA * 16;
        } else {
            int gr = min(mtile * 128 + rA, cnt - 1);
            asrc[i] = (const char*)(hsrc + (size_t)(base + gr) * Kd) + lsubA * 16;
        }
        int rB = lrowB + 16 * i;
        dstoffB[i] = (uint32_t)(rB * 256 + ((lsubB ^ (rB & 7)) << 4));
        bsrc[i] = (const char*)(WhE + (size_t)rB * Nd) + lsubB * 16;
    }
    const size_t bstep = (size_t)KC * Nd * sizeof(__half);  // per-stage B advance

    // ---- ldmatrix lane constants ----
    const int til = lid >> 3, rin = lid & 7;
    const int thi = til >> 1, tlo = til & 1;
    uint32_t rowbaseA[4];
#pragma unroll
    for (int mt = 0; mt < 4; mt++)
        rowbaseA[mt] = (uint32_t)((m0 + mt * 16 + rin + tlo * 8) * 128);
    uint32_t koffA[4];
#pragma unroll
    for (int ks = 0; ks < 4; ks++)
        koffA[ks] = (uint32_t)((((ks * 2) + thi) ^ rin) << 4);
    const int klane = rin + tlo * 8;   // 0..15
    uint32_t lbB[2];
#pragma unroll
    for (int pr = 0; pr < 2; pr++) {
        int nc = (n0 >> 3) + pr * 2 + thi;
        lbB[pr] = (uint32_t)(klane * 256 + ((nc ^ (klane & 7)) << 4));
    }

    float acc[4][4][4];
#pragma unroll
    for (int mt = 0; mt < 4; mt++)
#pragma unroll
        for (int nt = 0; nt < 4; nt++)
#pragma unroll
            for (int c = 0; c < 4; c++) acc[mt][nt][c] = 0.0f;

    auto issue = [&](int s) {
        uint32_t sa = sb + HDR_BYTES + (s % NSTAGE) * STAGE_BYTES;
        uint32_t sB = sa + 16384;
        size_t aoff = (size_t)s * 128;       // 64 halves = 128 bytes along K
        size_t boff = (size_t)s * bstep;
#pragma unroll
        for (int i = 0; i < 4; i++) CP_ASYNC16(sa + dstoffA[i], asrc[i] + aoff);
#pragma unroll
        for (int i = 0; i < 4; i++) CP_ASYNC16_CG(sB + dstoffB[i], bsrc[i] + boff);
    };

    issue(0); CP_COMMIT();
    issue(1); CP_COMMIT();

    for (int c = 0; c < NCH; c++) {
        if (c + 1 < NCH) { CP_WAIT1(); } else { CP_WAIT0(); }
        __syncthreads();
        if (c + 2 < NCH) { issue(c + 2); CP_COMMIT(); }

        uint32_t sa = sb + HDR_BYTES + (c % NSTAGE) * STAGE_BYTES;
        uint32_t sB = sa + 16384;
#pragma unroll
        for (int ks = 0; ks < 4; ks++) {
            uint32_t b[8];
            ldsm_x4_t(b[0], b[1], b[2], b[3], sB + lbB[0] + ks * 4096);
            ldsm_x4_t(b[4], b[5], b[6], b[7], sB + lbB[1] + ks * 4096);
#pragma unroll
            for (int mt = 0; mt < 4; mt++) {
                uint32_t a0, a1, a2, a3;
                ldsm_x4(a0, a1, a2, a3, sa + rowbaseA[mt] + koffA[ks]);
                mma_f16(acc[mt][0][0], acc[mt][0][1], acc[mt][0][2], acc[mt][0][3],
                        a0, a1, a2, a3, b[0], b[1]);
                mma_f16(acc[mt][1][0], acc[mt][1][1], acc[mt][1][2], acc[mt][1][3],
                        a0, a1, a2, a3, b[2], b[3]);
                mma_f16(acc[mt][2][0], acc[mt][2][1], acc[mt][2][2], acc[mt][2][3],
                        a0, a1, a2, a3, b[4], b[5]);
                mma_f16(acc[mt][3][0], acc[mt][3][1], acc[mt][3][2], acc[mt][3][3],
                        a0, a1, a2, a3, b[6], b[7]);
            }
        }
    }

    // ---- epilogue ----
    const float* biasE = bias + (size_t)e * Nd + nblk * 128;
    __half* hdst = (LAYER == 1) ? d_h1 : d_h2;

#pragma unroll
    for (int mt = 0; mt < 4; mt++) {
#pragma unroll
        for (int nt = 0; nt < 4; nt++) {
            int col = n0 + nt * 8 + tg * 2;
            float bv0 = biasE[col], bv1 = biasE[col + 1];
#pragma unroll
            for (int half = 0; half < 2; half++) {
                int lr = m0 + mt * 16 + g + half * 8;
                int grow = mtile * 128 + lr;
                if (grow >= cnt) continue;
                float v0 = acc[mt][nt][half * 2 + 0] + bv0;
                float v1 = acc[mt][nt][half * 2 + 1] + bv1;
                if (LAYER != 3) {
                    __half2 v = __floats2half2_rn(fmaxf(v0, 0.0f), fmaxf(v1, 0.0f));
                    *(__half2*)(hdst + (size_t)(base + grow) * HH + nblk * 128 + col) = v;
                } else {
                    float gt = sgate[lr];
                    float2 v = make_float2(gt * v0, gt * v1);
                    *(float2*)(d_y + (size_t)(base + grow) * OO + nblk * 128 + col) = v;
                }
            }
        }
    }
}

// ================= combine: out[t] = y[pos(2t)] + y[pos(2t+1)] =================
__global__ void combine_kernel(float* __restrict__ out) {
    int t = blockIdx.x;
    int p0 = d_pair_pos[2 * t];
    int p1 = d_pair_pos[2 * t + 1];
    const float4* y0 = (const float4*)(d_y + (size_t)p0 * OO);
    const float4* y1 = (const float4*)(d_y + (size_t)p1 * OO);
    float4* dst = (float4*)(out + (size_t)t * OO);
    int i = threadIdx.x;             // 256 threads, 256 float4 per row
    float4 a = y0[i], b = y1[i];
    dst[i] = make_float4(a.x + b.x, a.y + b.y, a.z + b.z, a.w + b.w);
}

// ================= launch =================
extern "C" void kernel_launch(void* const* d_in, const int* in_sizes, int n_in,
                              void* d_out, int out_size) {
    const float* x  = (const float*)d_in[0];
    const float* Wg = (const float*)d_in[1];
    const float* bg = (const float*)d_in[2];
    const float* W1 = (const float*)d_in[3];
    const float* b1 = (const float*)d_in[4];
    const float* W2 = (const float*)d_in[5];
    const float* b2 = (const float*)d_in[6];
    const float* W3 = (const float*)d_in[7];
    const float* b3 = (const float*)d_in[8];
    float* out = (float*)d_out;

    cudaFuncSetAttribute(expert_gemm_mma<1>, cudaFuncAttributeMaxDynamicSharedMemorySize, SMEM_DYN);
    cudaFuncSetAttribute(expert_gemm_mma<2>, cudaFuncAttributeMaxDynamicSharedMemorySize, SMEM_DYN);
    cudaFuncSetAttribute(expert_gemm_mma<3>, cudaFuncAttributeMaxDynamicSharedMemorySize, SMEM_DYN);

    __half* w1h = nullptr; cudaGetSymbolAddress((void**)&w1h, d_w1h);
    __half* w2h = nullptr; cudaGetSymbolAddress((void**)&w2h, d_w2h);
    __half* w3h = nullptr; cudaGetSymbolAddress((void**)&w3h, d_w3h);

    init_acc_kernel<<<1, 32>>>();                                         // 1
    convert_w_kernel<<<(unsigned)((N1 + N2 + N3) / 8 / 256), 256>>>(W1, W2, W3); // 2
    gating_kernel<<<BT, 128>>>(x, Wg, bg);                                // 3
    finalize_kernel<<<1, 32>>>(out, out_size);                            // 4
    scatter_kernel<<<NPAIR / 256, 256>>>();                               // 5
    expert_gemm_mma<1><<<dim3(HH/128, 32, EE), 256, SMEM_DYN>>>(w1h, b1); // 6 -> ncu
    expert_gemm_mma<2><<<dim3(HH/128, 32, EE), 256, SMEM_DYN>>>(w2h, b2); // 7
    expert_gemm_mma<3><<<dim3(OO/128, 32, EE), 256, SMEM_DYN>>>(w3h, b3); // 8
    combine_kernel<<<BT, 256>>>(out);                                     // 9
}

// round 14
// speedup vs baseline: 1.1195x; 1.0184x over previous
#include <cuda_runtime.h>
#include <cuda_fp16.h>
#include <cuda_bf16.h>
#include <math.h>
#include <stdint.h>

// Problem constants
#define BT   4096      // B*S tokens
#define DD   1024
#define HH   2048
#define OO   1024
#define EE   8
#define TOPK 2
#define NPAIR (BT*TOPK)    // 8192
#define OUT_TENSOR (BT*OO) // 4194304

// ================= small helpers =================
__device__ __forceinline__ uint32_t smem_to_u32(const void* p) {
    uint32_t a;
    asm("{ .reg .u64 t; cvta.to.shared.u64 t, %1; cvt.u32.u64 %0, t; }" : "=r"(a) : "l"(p));
    return a;
}
#define CP_ASYNC16(dst, src) \
    asm volatile("cp.async.ca.shared.global [%0], [%1], 16;" :: "r"(dst), "l"(src))
#define CP_ASYNC16_CG(dst, src) \
    asm volatile("cp.async.cg.shared.global [%0], [%1], 16;" :: "r"(dst), "l"(src))
#define CP_COMMIT() asm volatile("cp.async.commit_group;" ::: "memory")
#define CP_WAIT1()  asm volatile("cp.async.wait_group 1;" ::: "memory")
#define CP_WAIT0()  asm volatile("cp.async.wait_group 0;" ::: "memory")

__device__ __forceinline__ void ldsm_x4(uint32_t& r0, uint32_t& r1, uint32_t& r2, uint32_t& r3,
                                        uint32_t addr) {
    asm volatile("ldmatrix.sync.aligned.m8n8.x4.shared.b16 {%0,%1,%2,%3}, [%4];"
                 : "=r"(r0), "=r"(r1), "=r"(r2), "=r"(r3) : "r"(addr));
}
__device__ __forceinline__ void ldsm_x4_t(uint32_t& r0, uint32_t& r1, uint32_t& r2, uint32_t& r3,
                                          uint32_t addr) {
    asm volatile("ldmatrix.sync.aligned.m8n8.x4.trans.shared.b16 {%0,%1,%2,%3}, [%4];"
                 : "=r"(r0), "=r"(r1), "=r"(r2), "=r"(r3) : "r"(addr));
}
__device__ __forceinline__ void mma_f16(float& c0, float& c1, float& c2, float& c3,
                                        uint32_t a0, uint32_t a1, uint32_t a2, uint32_t a3,
                                        uint32_t b0, uint32_t b1) {
    asm volatile(
        "mma.sync.aligned.m16n8k16.row.col.f32.f16.f16.f32 "
        "{%0,%1,%2,%3}, {%4,%5,%6,%7}, {%8,%9}, {%0,%1,%2,%3};"
        : "+f"(c0), "+f"(c1), "+f"(c2), "+f"(c3)
        : "r"(a0), "r"(a1), "r"(a2), "r"(a3), "r"(b0), "r"(b1));
}

// ================= scratch =================
__device__ __half d_h1[(size_t)NPAIR * HH];          // 32 MB
__device__ __half d_h2[(size_t)NPAIR * HH];          // 32 MB
__device__ __half d_xh[(size_t)BT * DD];             // 8 MB (fp16 x)
__device__ __half d_w1h[(size_t)EE * DD * HH];       // 32 MB  [E][D][H] (K x N row-major)
__device__ __half d_w2h[(size_t)EE * HH * HH];       // 64 MB
__device__ __half d_w3h[(size_t)EE * HH * OO];       // 32 MB
__device__ float  d_y[(size_t)NPAIR * OO];           // 32 MB gated partial outputs by position
__device__ int   d_pair_token[NPAIR];
__device__ float d_pair_gate[NPAIR];
__device__ int   d_pair_pos[NPAIR];                  // pair j -> position
__device__ int   d_counts[EE];
__device__ int   d_offsets[EE];
__device__ int   d_cursor[EE];
__device__ float d_sum_probs[EE];
__device__ float d_sum_gates[EE];
__device__ int   d_top_idx[NPAIR];
__device__ float d_top_g[NPAIR];

#define N1 ((size_t)EE * DD * HH)   // 16,777,216
#define N2 ((size_t)EE * HH * HH)   // 33,554,432
#define N3 ((size_t)EE * HH * OO)   // 16,777,216

// ---- shared fp32->fp16 convert of 8 contiguous elements ----
__device__ __forceinline__ void conv8(const float* __restrict__ src,
                                      __half* __restrict__ dst, size_t off) {
    float4 f0 = *(const float4*)(src + off);
    float4 f1 = *(const float4*)(src + off + 4);
    __half2 h[4];
    h[0] = __floats2half2_rn(f0.x, f0.y);
    h[1] = __floats2half2_rn(f0.z, f0.w);
    h[2] = __floats2half2_rn(f1.x, f1.y);
    h[3] = __floats2half2_rn(f1.z, f1.w);
    *(uint4*)(dst + off) = *(uint4*)h;
}

// ================= fat pre: W1 convert + gating (emits fp16 x) ==============
#define NCONV1B 8192u    // N1 / (256*8)
__global__ __launch_bounds__(256)
void fatpre_kernel(const float* __restrict__ W1,
                   const float* __restrict__ x,
                   const float* __restrict__ Wg,
                   const float* __restrict__ bg) {
    if (blockIdx.x < NCONV1B) {
        size_t i8 = ((size_t)blockIdx.x * 256 + threadIdx.x) * 8;
        conv8(W1, d_w1h, i8);
        return;
    }
    // -------- gating: one token per block, 256 threads --------
    int t = blockIdx.x - NCONV1B;
    int tid = threadIdx.x;
    float acc[EE];
#pragma unroll
    for (int e = 0; e < EE; e++) acc[e] = 0.0f;
    const float* xr = x + (size_t)t * DD;
    __half* xh = d_xh + (size_t)t * DD;
    for (int d = tid; d < DD; d += 256) {
        float xv = xr[d];
        xh[d] = __float2half(xv);
        const float* w = Wg + (size_t)d * EE;
#pragma unroll
        for (int e = 0; e < EE; e++) acc[e] += xv * w[e];
    }
#pragma unroll
    for (int e = 0; e < EE; e++) {
#pragma unroll
        for (int off = 16; off > 0; off >>= 1)
            acc[e] += __shfl_down_sync(0xffffffffu, acc[e], off);
    }
    __shared__ float sred[8][EE];
    int warp = tid >> 5, lane = tid & 31;
    if (lane == 0) {
#pragma unroll
        for (int e = 0; e < EE; e++) sred[warp][e] = acc[e];
    }
    __syncthreads();
    if (tid == 0) {
        float logit[EE];
#pragma unroll
        for (int e = 0; e < EE; e++) {
            float s = sred[0][e];
#pragma unroll
            for (int w = 1; w < 8; w++) s += sred[w][e];
            logit[e] = s + bg[e];
        }
        float m = logit[0];
#pragma unroll
        for (int e = 1; e < EE; e++) m = fmaxf(m, logit[e]);
        float p[EE], se = 0.0f;
#pragma unroll
        for (int e = 0; e < EE; e++) { p[e] = __expf(logit[e] - m); se += p[e]; }
        float inv = 1.0f / se;
#pragma unroll
        for (int e = 0; e < EE; e++) atomicAdd(&d_sum_probs[e], p[e] * inv);
        int i0 = 0;
#pragma unroll
        for (int e = 1; e < EE; e++) if (logit[e] > logit[i0]) i0 = e;
        int i1 = (i0 == 0) ? 1 : 0;
#pragma unroll
        for (int e = 0; e < EE; e++)
            if (e != i0 && logit[e] > logit[i1]) i1 = e;
        float l0 = logit[i0], l1 = logit[i1];
        float mm = fmaxf(l0, l1);
        float e0 = __expf(l0 - mm), e1 = __expf(l1 - mm);
        float s2 = e0 + e1;
        float g0 = e0 / s2, g1 = e1 / s2;
        atomicAdd(&d_sum_gates[i0], g0);
        atomicAdd(&d_sum_gates[i1], g1);
        atomicAdd(&d_counts[i0], 1);
        atomicAdd(&d_counts[i1], 1);
        d_top_idx[t * 2 + 0] = i0;  d_top_g[t * 2 + 0] = g0;
        d_top_idx[t * 2 + 1] = i1;  d_top_g[t * 2 + 1] = g1;
    }
}

// tiny init for accumulators (before gating)
__global__ void init_acc_kernel() {
    if (threadIdx.x < EE) {
        d_counts[threadIdx.x] = 0;
        d_sum_probs[threadIdx.x] = 0.0f;
        d_sum_gates[threadIdx.x] = 0.0f;
    }
}

// ================= finalize: offsets + aux stats + tail-zero =================
__global__ void finalize_kernel(float* __restrict__ out, int out_size) {
    if (threadIdx.x == 0 && blockIdx.x == 0) {
        int off = 0;
        for (int e = 0; e < EE; e++) {
            d_offsets[e] = off;
            off += d_counts[e];
            d_cursor[e] = 0;
        }
        for (int i = OUT_TENSOR; i < out_size; i++) out[i] = 0.0f;  // tail is tiny
        float lb = 0.0f, ent = 0.0f;
        const float invT = 1.0f / (float)BT;
        for (int e = 0; e < EE; e++) {
            float ap = d_sum_probs[e] * invT;
            float ac = d_sum_gates[e] * invT;
            lb += ap * ac;
            ent -= ap * logf(ap + 1e-8f);
            out[OUT_TENSOR + 1 + e] = ac;
        }
        out[OUT_TENSOR] = 0.01f * (float)EE * lb;
        out[OUT_TENSOR + 1 + EE] = ent;
    }
}

// ================= scatter =================
__global__ void scatter_kernel() {
    int j = blockIdx.x * blockDim.x + threadIdx.x;
    if (j >= NPAIR) return;
    int t = j >> 1;
    int e = d_top_idx[j];
    int pos = d_offsets[e] + atomicAdd(&d_cursor[e], 1);
    d_pair_token[pos] = t;
    d_pair_gate[pos]  = d_top_g[j];
    d_pair_pos[j] = pos;
}

// ================= fp16 mma.sync expert GEMM (ldmatrix + 3-stage cp.async) ========
// CTA 128(M)x128(N), KC=64. warp grid 2m x 4n; warp tile 64x32; mma m16n8k16 f32-acc.
// blockIdx.z >= EE -> piggyback fp32->fp16 conversion of NEXT layer's weights.
#define KC 64
#define STAGE_BYTES 32768            // A 16KB + B 16KB
#define HDR_BYTES 1024
#define NSTAGE 3
#define SMEM_DYN (HDR_BYTES + NSTAGE*STAGE_BYTES)

template<int LAYER>
__global__ __launch_bounds__(256, 2)
void expert_gemm_mma(const __half* __restrict__ Wh,
                     const float* __restrict__ bias,
                     const float* __restrict__ convsrc,
                     __half* __restrict__ convdst,
                     size_t convN) {
    constexpr int Kd = (LAYER == 1) ? DD : HH;
    constexpr int Nd = (LAYER == 3) ? OO : HH;
    constexpr int NCH = Kd / KC;   // 16 or 32

    if (blockIdx.z >= EE) {
        // -------- piggyback weight conversion for the next layer --------
        size_t cb = ((size_t)(blockIdx.z - EE) * gridDim.y + blockIdx.y) * gridDim.x + blockIdx.x;
        size_t i8 = (cb * 256 + threadIdx.x) * 8;
        if (i8 < convN) conv8(convsrc, convdst, i8);
        return;
    }

    const int e   = blockIdx.z;
    const int cnt = d_counts[e];
    const int mtile = blockIdx.y;
    if (mtile * 128 >= cnt) return;
    const int base = d_offsets[e];
    const int nblk = blockIdx.x;

    extern __shared__ char smem_raw[];
    const uint32_t sb = smem_to_u32(smem_raw);
    int* stok    = (int*)smem_raw;            // [128]
    float* sgate = (float*)(smem_raw + 512);  // [128]

    const int tid = threadIdx.x;
    const int wid = tid >> 5;
    const int lid = tid & 31;
    const int g   = lid >> 2;     // 0..7
    const int tg  = lid & 3;      // 0..3
    const int m0  = (wid & 1) * 64;
    const int n0  = (wid >> 1) * 32;

    if (tid < 128) {
        int gr = mtile * 128 + tid;
        int idx = base + min(gr, cnt - 1);
        stok[tid]  = d_pair_token[idx];
        sgate[tid] = d_pair_gate[idx];
    }
    __syncthreads();

    // ---- cp.async mappings ----
    const int lsubA = tid & 7, lrowA = tid >> 3;     // A: 128 rows x 128B
    const int lsubB = tid & 15, lrowB = tid >> 4;    // B: 64 rows x 256B

    const __half* WhE = Wh + (size_t)e * Kd * Nd + (size_t)(nblk * 128);
    const __half* hsrc = (LAYER == 2) ? d_h1 : d_h2;

    uint32_t dstoffA[4], dstoffB[4];
    const char* asrc[4];
    const char* bsrc[4];
#pragma unroll
    for (int i = 0; i < 4; i++) {
        int rA = lrowA + 32 * i;
        dstoffA[i] = (uint32_t)(rA * 128 + ((lsubA ^ (rA & 7)) << 4));
        if (LAYER == 1) {
            asrc[i] = (const char*)(d_xh + (size_t)stok[rA] * DD) + lsubA * 16;
        } else {
            int gr = min(mtile * 128 + rA, cnt - 1);
            asrc[i] = (const char*)(hsrc + (size_t)(base + gr) * Kd) + lsubA * 16;
        }
        int rB = lrowB + 16 * i;
        dstoffB[i] = (uint32_t)(rB * 256 + ((lsubB ^ (rB & 7)) << 4));
        bsrc[i] = (const char*)(WhE + (size_t)rB * Nd) + lsubB * 16;
    }
    const size_t bstep = (size_t)KC * Nd * sizeof(__half);  // per-stage B advance

    // ---- ldmatrix lane constants ----
    const int til = lid >> 3, rin = lid & 7;
    const int thi = til >> 1, tlo = til & 1;
    uint32_t rowbaseA[4];
#pragma unroll
    for (int mt = 0; mt < 4; mt++)
        rowbaseA[mt] = (uint32_t)((m0 + mt * 16 + rin + tlo * 8) * 128);
    uint32_t koffA[4];
#pragma unroll
    for (int ks = 0; ks < 4; ks++)
        koffA[ks] = (uint32_t)((((ks * 2) + thi) ^ rin) << 4);
    const int klane = rin + tlo * 8;   // 0..15
    uint32_t lbB[2];
#pragma unroll
    for (int pr = 0; pr < 2; pr++) {
        int nc = (n0 >> 3) + pr * 2 + thi;
        lbB[pr] = (uint32_t)(klane * 256 + ((nc ^ (klane & 7)) << 4));
    }

    float acc[4][4][4];
#pragma unroll
    for (int mt = 0; mt < 4; mt++)
#pragma unroll
        for (int nt = 0; nt < 4; nt++)
#pragma unroll
            for (int c = 0; c < 4; c++) acc[mt][nt][c] = 0.0f;

    auto issue = [&](int s) {
        uint32_t sa = sb + HDR_BYTES + (s % NSTAGE) * STAGE_BYTES;
        uint32_t sB = sa + 16384;
        size_t aoff = (size_t)s * 128;       // 64 halves = 128 bytes along K
        size_t boff = (size_t)s * bstep;
#pragma unroll
        for (int i = 0; i < 4; i++) CP_ASYNC16(sa + dstoffA[i], asrc[i] + aoff);
#pragma unroll
        for (int i = 0; i < 4; i++) CP_ASYNC16_CG(sB + dstoffB[i], bsrc[i] + boff);
    };

    issue(0); CP_COMMIT();
    issue(1); CP_COMMIT();

    for (int c = 0; c < NCH; c++) {
        if (c + 1 < NCH) { CP_WAIT1(); } else { CP_WAIT0(); }
        __syncthreads();
        if (c + 2 < NCH) { issue(c + 2); CP_COMMIT(); }

        uint32_t sa = sb + HDR_BYTES + (c % NSTAGE) * STAGE_BYTES;
        uint32_t sB = sa + 16384;
#pragma unroll
        for (int ks = 0; ks < 4; ks++) {
            uint32_t b[8];
            ldsm_x4_t(b[0], b[1], b[2], b[3], sB + lbB[0] + ks * 4096);
            ldsm_x4_t(b[4], b[5], b[6], b[7], sB + lbB[1] + ks * 4096);
#pragma unroll
            for (int mt = 0; mt < 4; mt++) {
                uint32_t a0, a1, a2, a3;
                ldsm_x4(a0, a1, a2, a3, sa + rowbaseA[mt] + koffA[ks]);
                mma_f16(acc[mt][0][0], acc[mt][0][1], acc[mt][0][2], acc[mt][0][3],
                        a0, a1, a2, a3, b[0], b[1]);
                mma_f16(acc[mt][1][0], acc[mt][1][1], acc[mt][1][2], acc[mt][1][3],
                        a0, a1, a2, a3, b[2], b[3]);
                mma_f16(acc[mt][2][0], acc[mt][2][1], acc[mt][2][2], acc[mt][2][3],
                        a0, a1, a2, a3, b[4], b[5]);
                mma_f16(acc[mt][3][0], acc[mt][3][1], acc[mt][3][2], acc[mt][3][3],
                        a0, a1, a2, a3, b[6], b[7]);
            }
        }
    }

    // ---- epilogue ----
    const float* biasE = bias + (size_t)e * Nd + nblk * 128;
    __half* hdst = (LAYER == 1) ? d_h1 : d_h2;

#pragma unroll
    for (int mt = 0; mt < 4; mt++) {
#pragma unroll
        for (int nt = 0; nt < 4; nt++) {
            int col = n0 + nt * 8 + tg * 2;
            float bv0 = biasE[col], bv1 = biasE[col + 1];
#pragma unroll
            for (int half = 0; half < 2; half++) {
                int lr = m0 + mt * 16 + g + half * 8;
                int grow = mtile * 128 + lr;
                if (grow >= cnt) continue;
                float v0 = acc[mt][nt][half * 2 + 0] + bv0;
                float v1 = acc[mt][nt][half * 2 + 1] + bv1;
                if (LAYER != 3) {
                    __half2 v = __floats2half2_rn(fmaxf(v0, 0.0f), fmaxf(v1, 0.0f));
                    *(__half2*)(hdst + (size_t)(base + grow) * HH + nblk * 128 + col) = v;
                } else {
                    float gt = sgate[lr];
                    float2 v = make_float2(gt * v0, gt * v1);
                    *(float2*)(d_y + (size_t)(base + grow) * OO + nblk * 128 + col) = v;
                }
            }
        }
    }
}

// ================= combine: out[t] = y[pos(2t)] + y[pos(2t+1)] =================
__global__ void combine_kernel(float* __restrict__ out) {
    int t = blockIdx.x;
    int p0 = d_pair_pos[2 * t];
    int p1 = d_pair_pos[2 * t + 1];
    const float4* y0 = (const float4*)(d_y + (size_t)p0 * OO);
    const float4* y1 = (const float4*)(d_y + (size_t)p1 * OO);
    float4* dst = (float4*)(out + (size_t)t * OO);
    int i = threadIdx.x;             // 256 threads, 256 float4 per row
    float4 a = y0[i], b = y1[i];
    dst[i] = make_float4(a.x + b.x, a.y + b.y, a.z + b.z, a.w + b.w);
}

// ================= launch =================
extern "C" void kernel_launch(void* const* d_in, const int* in_sizes, int n_in,
                              void* d_out, int out_size) {
    const float* x  = (const float*)d_in[0];
    const float* Wg = (const float*)d_in[1];
    const float* bg = (const float*)d_in[2];
    const float* W1 = (const float*)d_in[3];
    const float* b1 = (const float*)d_in[4];
    const float* W2 = (const float*)d_in[5];
    const float* b2 = (const float*)d_in[6];
    const float* W3 = (const float*)d_in[7];
    const float* b3 = (const float*)d_in[8];
    float* out = (float*)d_out;

    cudaFuncSetAttribute(expert_gemm_mma<1>, cudaFuncAttributeMaxDynamicSharedMemorySize, SMEM_DYN);
    cudaFuncSetAttribute(expert_gemm_mma<2>, cudaFuncAttributeMaxDynamicSharedMemorySize, SMEM_DYN);
    cudaFuncSetAttribute(expert_gemm_mma<3>, cudaFuncAttributeMaxDynamicSharedMemorySize, SMEM_DYN);

    __half* w1h = nullptr; cudaGetSymbolAddress((void**)&w1h, d_w1h);
    __half* w2h = nullptr; cudaGetSymbolAddress((void**)&w2h, d_w2h);
    __half* w3h = nullptr; cudaGetSymbolAddress((void**)&w3h, d_w3h);

    // conv block counts piggybacked on gemm grids:
    // gemm1 carries W2: N2/(256*8) = 16384 blocks = 32 z-slices of 16x32
    // gemm2 carries W3: N3/(256*8) =  8192 blocks = 16 z-slices of 16x32
    init_acc_kernel<<<1, 32>>>();                                           // 1
    fatpre_kernel<<<NCONV1B + BT, 256>>>(W1, x, Wg, bg);                    // 2 (W1 conv + gating)
    finalize_kernel<<<1, 32>>>(out, out_size);                              // 3
    scatter_kernel<<<NPAIR / 256, 256>>>();                                 // 4
    expert_gemm_mma<1><<<dim3(HH/128, 32, EE + 32), 256, SMEM_DYN>>>(w1h, b1, W2, w2h, N2); // 5
    expert_gemm_mma<2><<<dim3(HH/128, 32, EE + 16), 256, SMEM_DYN>>>(w2h, b2, W3, w3h, N3); // 6 -> ncu
    expert_gemm_mma<3><<<dim3(OO/128, 32, EE), 256, SMEM_DYN>>>(w3h, b3, nullptr, nullptr, 0); // 7
    combine_kernel<<<BT, 256>>>(out);                                       // 8
}